// round 1
// baseline (speedup 1.0000x reference)
#include <cuda_runtime.h>
#include <cstdint>
#include <cstddef>

// Problem constants
#define NN   2048
#define KNB  48
#define NF   384
#define MIN_ 1536
#define NROWS (NN*KNB)        // 98304
#define LAYERS 3

// -------- device scratch (no allocations allowed) --------
__device__ float g_H1[(size_t)NROWS * NF];
__device__ float g_H2[(size_t)NROWS * NF];
__device__ float g_A [NN * NF];
__device__ float g_C [NN * NF];
__device__ float g_S [NN * NF];
__device__ float g_AGG[NN * NF];
__device__ float g_X [NN * NF];
__device__ float g_X1[NN * NF];
__device__ float g_D [NN * NF];
__device__ float g_T [NN * MIN_];

// -------- helpers --------
__device__ __forceinline__ uint32_t f2tf(float x) {
    uint32_t r;
    asm("cvt.rna.tf32.f32 %0, %1;" : "=r"(r) : "f"(x));
    return r;
}

__device__ __forceinline__ void mma_tf32(float* c, const uint32_t* a, const uint32_t* b) {
    asm volatile(
        "mma.sync.aligned.m16n8k8.row.col.f32.tf32.tf32.f32 "
        "{%0,%1,%2,%3}, {%4,%5,%6,%7}, {%8,%9}, {%0,%1,%2,%3};\n"
        : "+f"(c[0]), "+f"(c[1]), "+f"(c[2]), "+f"(c[3])
        : "r"(a[0]), "r"(a[1]), "r"(a[2]), "r"(a[3]),
          "r"(b[0]), "r"(b[1]));
}

__device__ __forceinline__ float gelu_exact(float x) {
    return 0.5f * x * (1.0f + erff(x * 0.70710678118654752440f));
}

// -------- generic TF32 GEMM: D[M,N] = epilogue(A[M,K] @ B[K,N]) --------
// epilogue modes:
//   addA != nullptr  => v += addA[(m/48)*N + n] + addC[idxFlat[m]*N + n]  (message gemm0)
//   bias != nullptr  => v = alpha*acc + beta*bias[n]   else v = alpha*acc
//   doGelu           => v = gelu(v)
#define BM 128
#define BN 64
#define BK 32

__global__ __launch_bounds__(256) void gemm_tf32_kernel(
    const float* __restrict__ A, const float* __restrict__ B,
    float* __restrict__ D, int M, int N, int K,
    const float* __restrict__ bias, float alpha, float beta, int doGelu,
    const float* __restrict__ addA, const float* __restrict__ addC,
    const int* __restrict__ idxFlat)
{
    __shared__ uint32_t As[BM][BK + 4];   // 36 words/row (16B aligned)
    __shared__ uint32_t Bs[BK][BN + 4];   // 68 words/row (16B aligned)

    const int tid  = threadIdx.x;
    const int m0   = blockIdx.x * BM;
    const int n0   = blockIdx.y * BN;
    const int warp = tid >> 5;
    const int lane = tid & 31;
    const int wm   = warp >> 1;   // 0..3
    const int wn   = warp & 1;    // 0..1
    const int gid  = lane >> 2;   // 0..7
    const int tig  = lane & 3;    // 0..3

    float acc[2][4][4];
    #pragma unroll
    for (int a = 0; a < 2; a++)
        #pragma unroll
        for (int b = 0; b < 4; b++)
            #pragma unroll
            for (int c = 0; c < 4; c++)
                acc[a][b][c] = 0.f;

    for (int k0 = 0; k0 < K; k0 += BK) {
        // ---- load A tile (128x32): 4 float4 per thread ----
        #pragma unroll
        for (int r = 0; r < 4; r++) {
            int lin = tid + r * 256;      // 0..1023
            int row = lin >> 3;           // 0..127
            int c4  = lin & 7;            // 0..7
            int gm  = m0 + row;
            float4 v;
            if (gm < M) v = *(const float4*)(A + (size_t)gm * K + k0 + c4 * 4);
            else        v = make_float4(0.f, 0.f, 0.f, 0.f);
            uint32_t* dst = &As[row][c4 * 4];
            dst[0] = f2tf(v.x); dst[1] = f2tf(v.y);
            dst[2] = f2tf(v.z); dst[3] = f2tf(v.w);
        }
        // ---- load B tile (32x64): 2 float4 per thread ----
        #pragma unroll
        for (int r = 0; r < 2; r++) {
            int lin = tid + r * 256;      // 0..511
            int row = lin >> 4;           // 0..31
            int c4  = lin & 15;           // 0..15
            int gk  = k0 + row;
            int gn  = n0 + c4 * 4;
            float4 v;
            if (gk < K && gn < N) v = *(const float4*)(B + (size_t)gk * N + gn);
            else                  v = make_float4(0.f, 0.f, 0.f, 0.f);
            uint32_t* dst = &Bs[row][c4 * 4];
            dst[0] = f2tf(v.x); dst[1] = f2tf(v.y);
            dst[2] = f2tf(v.z); dst[3] = f2tf(v.w);
        }
        __syncthreads();

        #pragma unroll
        for (int kk = 0; kk < 4; kk++) {
            uint32_t afr[2][4], bfr[4][2];
            #pragma unroll
            for (int mi = 0; mi < 2; mi++) {
                int mb = wm * 32 + mi * 16;
                int kc = kk * 8 + tig;
                afr[mi][0] = As[mb + gid    ][kc    ];
                afr[mi][1] = As[mb + gid + 8][kc    ];
                afr[mi][2] = As[mb + gid    ][kc + 4];
                afr[mi][3] = As[mb + gid + 8][kc + 4];
            }
            #pragma unroll
            for (int ni = 0; ni < 4; ni++) {
                int nb = wn * 32 + ni * 8;
                bfr[ni][0] = Bs[kk * 8 + tig    ][nb + gid];
                bfr[ni][1] = Bs[kk * 8 + tig + 4][nb + gid];
            }
            #pragma unroll
            for (int mi = 0; mi < 2; mi++)
                #pragma unroll
                for (int ni = 0; ni < 4; ni++)
                    mma_tf32(acc[mi][ni], afr[mi], bfr[ni]);
        }
        __syncthreads();
    }

    // ---- epilogue ----
    #pragma unroll
    for (int mi = 0; mi < 2; mi++) {
        #pragma unroll
        for (int h = 0; h < 2; h++) {
            int m = m0 + wm * 32 + mi * 16 + gid + h * 8;
            if (m >= M) continue;
            const float* aArow = nullptr;
            const float* aCrow = nullptr;
            if (addA) {
                aArow = addA + (size_t)(m / KNB) * N;
                aCrow = addC + (size_t)idxFlat[m] * N;
            }
            #pragma unroll
            for (int ni = 0; ni < 4; ni++) {
                int nbase = n0 + wn * 32 + ni * 8 + tig * 2;
                #pragma unroll
                for (int c = 0; c < 2; c++) {
                    int n = nbase + c;
                    float v = acc[mi][ni][h * 2 + c] * alpha;
                    if (bias) v += beta * bias[n];
                    if (aArow) v += aArow[n] + aCrow[n];
                    if (doGelu) v = gelu_exact(v);
                    D[(size_t)m * N + n] = v;
                }
            }
        }
    }
}

// -------- reduction over neighbors: S[i,n] = sum_k H2[i,k,n] --------
__global__ void reduce48_kernel(const float* __restrict__ H2, float* __restrict__ S) {
    int i = blockIdx.x;
    int n = threadIdx.x;                       // 384
    const float* p = H2 + (size_t)i * KNB * NF + n;
    float s = 0.f;
    #pragma unroll
    for (int k = 0; k < KNB; k++) s += p[(size_t)k * NF];
    S[(size_t)i * NF + n] = s;
}

// -------- layernorm over 384: out = [mask *] LN(a+b)*w + bv --------
__global__ void ln_kernel(const float* __restrict__ a, const float* __restrict__ b,
                          const float* __restrict__ w, const float* __restrict__ bv,
                          const float* __restrict__ mask, float* __restrict__ out)
{
    int i = blockIdx.x;
    int n = threadIdx.x;                       // 384
    float v = a[(size_t)i * NF + n] + b[(size_t)i * NF + n];

    __shared__ float s1[12], s2[12];
    float x1 = v, x2 = v * v;
    #pragma unroll
    for (int o = 16; o; o >>= 1) {
        x1 += __shfl_down_sync(0xFFFFFFFFu, x1, o);
        x2 += __shfl_down_sync(0xFFFFFFFFu, x2, o);
    }
    int wi = n >> 5, li = n & 31;
    if (li == 0) { s1[wi] = x1; s2[wi] = x2; }
    __syncthreads();
    __shared__ float mean_s, rstd_s;
    if (n == 0) {
        float t1 = 0.f, t2 = 0.f;
        #pragma unroll
        for (int j = 0; j < 12; j++) { t1 += s1[j]; t2 += s2[j]; }
        float mu  = t1 * (1.f / NF);
        float var = t2 * (1.f / NF) - mu * mu;
        mean_s = mu;
        rstd_s = rsqrtf(var + 1e-5f);
    }
    __syncthreads();
    float r = (v - mean_s) * rstd_s * w[n] + bv[n];
    if (mask) r *= mask[i];
    out[(size_t)i * NF + n] = r;
}

__global__ void copy_kernel(const float* __restrict__ src, float* __restrict__ dst, int n) {
    int i = blockIdx.x * blockDim.x + threadIdx.x;
    if (i < n) dst[i] = src[i];
}

// -------- host orchestration --------
static inline void launch_gemm(const float* A, const float* B, float* D,
                               int M, int N, int K,
                               const float* bias, float alpha, float beta, int doGelu,
                               const float* addA = nullptr, const float* addC = nullptr,
                               const int* idxFlat = nullptr)
{
    dim3 grid((M + BM - 1) / BM, N / BN);
    gemm_tf32_kernel<<<grid, 256>>>(A, B, D, M, N, K, bias, alpha, beta, doGelu,
                                    addA, addC, idxFlat);
}

extern "C" void kernel_launch(void* const* d_in, const int* in_sizes, int n_in,
                              void* d_out, int out_size)
{
    (void)in_sizes; (void)n_in; (void)out_size;

    const float* node  = (const float*)d_in[0];
    const float* edges = (const float*)d_in[1];     // [N,K,EF] -> [98304, 384]
    const int*   nidx  = (const int*)  d_in[2];     // [N,K] -> flat [98304]
    const float* mask  = (const float*)d_in[3];
    const float* w0    = (const float*)d_in[4];     // [L,1536,384]
    const float* b0    = (const float*)d_in[5];     // [L,384]
    const float* w1    = (const float*)d_in[6];     // [L,384,384]
    const float* b1    = (const float*)d_in[7];
    const float* w2    = (const float*)d_in[8];     // [L,384,384]
    const float* b2    = (const float*)d_in[9];
    const float* ln1w  = (const float*)d_in[10];
    const float* ln1b  = (const float*)d_in[11];
    const float* dw0   = (const float*)d_in[12];    // [L,384,1536]
    const float* db0   = (const float*)d_in[13];    // [L,1536]
    const float* dw1   = (const float*)d_in[14];    // [L,1536,384]
    const float* db1   = (const float*)d_in[15];
    const float* ln2w  = (const float*)d_in[16];
    const float* ln2b  = (const float*)d_in[17];

    float *H1, *H2, *Ab, *Cb, *Sb, *AGG, *X, *X1, *Dd, *T;
    cudaGetSymbolAddress((void**)&H1,  g_H1);
    cudaGetSymbolAddress((void**)&H2,  g_H2);
    cudaGetSymbolAddress((void**)&Ab,  g_A);
    cudaGetSymbolAddress((void**)&Cb,  g_C);
    cudaGetSymbolAddress((void**)&Sb,  g_S);
    cudaGetSymbolAddress((void**)&AGG, g_AGG);
    cudaGetSymbolAddress((void**)&X,   g_X);
    cudaGetSymbolAddress((void**)&X1,  g_X1);
    cudaGetSymbolAddress((void**)&Dd,  g_D);
    cudaGetSymbolAddress((void**)&T,   g_T);

    // x = node_features
    copy_kernel<<<(NN * NF + 255) / 256, 256>>>(node, X, NN * NF);

    for (int i = 0; i < LAYERS; i++) {
        const float* w0L  = w0  + (size_t)i * MIN_ * NF;
        const float* b0L  = b0  + (size_t)i * NF;
        const float* w1L  = w1  + (size_t)i * NF * NF;
        const float* b1L  = b1  + (size_t)i * NF;
        const float* w2L  = w2  + (size_t)i * NF * NF;
        const float* b2L  = b2  + (size_t)i * NF;
        const float* dw0L = dw0 + (size_t)i * NF * MIN_;
        const float* db0L = db0 + (size_t)i * MIN_;
        const float* dw1L = dw1 + (size_t)i * MIN_ * NF;
        const float* db1L = db1 + (size_t)i * NF;

        // (a) A = x @ W0[0:384] + b0          (per-node part of mlp_in)
        launch_gemm(X, w0L, Ab, NN, NF, NF, b0L, 1.f, 1.f, 0);
        // (b) C = node_features @ W0[1152:1536]  (gathered-neighbor part)
        launch_gemm(node, w0L + (size_t)1152 * NF, Cb, NN, NF, NF, nullptr, 1.f, 0.f, 0);
        // (c) H1 = gelu(edges @ W0[384:768] + A[i] + C[idx])   (zeros block skipped)
        launch_gemm(edges, w0L + (size_t)384 * NF, H1, NROWS, NF, NF,
                    nullptr, 1.f, 0.f, 1, Ab, Cb, nidx);
        // (d) H2 = gelu(H1 @ W1 + b1)
        launch_gemm(H1, w1L, H2, NROWS, NF, NF, b1L, 1.f, 1.f, 1);
        // (e) S = sum_k H2
        reduce48_kernel<<<NN, NF>>>(H2, Sb);
        // (f) AGG = (S @ W2 + 48*b2) / 30      (sum commutes with linear map)
        launch_gemm(Sb, w2L, AGG, NN, NF, NF, b2L, 1.f / 30.f, 48.f / 30.f, 0);
        // (g) x1 = LN(x + AGG)
        ln_kernel<<<NN, NF>>>(X, AGG, ln1w + (size_t)i * NF, ln1b + (size_t)i * NF,
                              nullptr, X1);
        // (h) T = gelu(x1 @ dense_w0 + db0)
        launch_gemm(X1, dw0L, T, NN, MIN_, NF, db0L, 1.f, 1.f, 1);
        // (i) D = T @ dense_w1 + db1
        launch_gemm(T, dw1L, Dd, NN, NF, MIN_, db1L, 1.f, 1.f, 0);
        // (j) x = mask * LN(x1 + D)
        float* xout = (i == LAYERS - 1) ? (float*)d_out : X;
        ln_kernel<<<NN, NF>>>(X1, Dd, ln2w + (size_t)i * NF, ln2b + (size_t)i * NF,
                              mask, xout);
    }
}

// round 2
// speedup vs baseline: 1.4632x; 1.4632x over previous
#include <cuda_runtime.h>
#include <cstdint>
#include <cstddef>

// Problem constants
#define NN   2048
#define KNB  48
#define NF   384
#define MIN_ 1536
#define NROWS (NN*KNB)        // 98304
#define LAYERS 3

// -------- device scratch (no allocations allowed) --------
__device__ float g_H1[(size_t)NROWS * NF];
__device__ float g_H2[(size_t)NROWS * NF];
__device__ float g_ET[(size_t)NROWS * NF];     // edges pre-rounded to tf32
__device__ float g_A  [NN * NF];
__device__ float g_C  [NN * NF];
__device__ float g_S  [NN * NF];
__device__ float g_AGG[NN * NF];
__device__ float g_X  [NN * NF];
__device__ float g_Xt [NN * NF];
__device__ float g_X1 [NN * NF];
__device__ float g_X1t[NN * NF];
__device__ float g_D  [NN * NF];
__device__ float g_T  [NN * MIN_];
__device__ float g_NT [NN * NF];               // node pre-rounded
__device__ float g_w0T [LAYERS * MIN_ * NF];
__device__ float g_w1T [LAYERS * NF * NF];
__device__ float g_w2T [LAYERS * NF * NF];
__device__ float g_dw0T[LAYERS * NF * MIN_];
__device__ float g_dw1T[LAYERS * MIN_ * NF];

// -------- helpers --------
__device__ __forceinline__ uint32_t f2tf(float x) {
    uint32_t r;
    asm("cvt.rna.tf32.f32 %0, %1;" : "=r"(r) : "f"(x));
    return r;
}

__device__ __forceinline__ void mma_tf32(float* c, const uint32_t* a, const uint32_t* b) {
    asm volatile(
        "mma.sync.aligned.m16n8k8.row.col.f32.tf32.tf32.f32 "
        "{%0,%1,%2,%3}, {%4,%5,%6,%7}, {%8,%9}, {%0,%1,%2,%3};\n"
        : "+f"(c[0]), "+f"(c[1]), "+f"(c[2]), "+f"(c[3])
        : "r"(a[0]), "r"(a[1]), "r"(a[2]), "r"(a[3]),
          "r"(b[0]), "r"(b[1]));
}

__device__ __forceinline__ float gelu_exact(float x) {
    return 0.5f * x * (1.0f + erff(x * 0.70710678118654752440f));
}

__device__ __forceinline__ void cp_async16(void* smem_dst, const void* gmem_src) {
    uint32_t s = (uint32_t)__cvta_generic_to_shared(smem_dst);
    asm volatile("cp.async.cg.shared.global [%0], [%1], 16;\n" :: "r"(s), "l"(gmem_src));
}
#define CP_COMMIT()  asm volatile("cp.async.commit_group;\n" ::: "memory")
#define CP_WAIT(n)   asm volatile("cp.async.wait_group %0;\n" :: "n"(n) : "memory")

// -------- TF32 GEMM: D[M,N] = epi(A[M,K] @ B[K,N]) --------
// All A/B operands must already be tf32-rounded fp32 bit patterns.
// flags: bit0 = gelu, bit1 = round output to tf32.
// addA != nullptr => v += addA[(m/48)*N+n] + addC[idxFlat[m]*N+n]
#define BM 128
#define BN 128
#define BK 32
#define SA 36     // As row stride (BK+4): bank(gid,tig)=4*gid+tig, bijective
#define SB 132    // Bs row stride (BN+4): bank(tig,gid)=4*tig+gid, bijective
#define AS_ELEMS (2*BM*SA)   // 9216 floats
#define GEMM_SMEM_BYTES ((AS_ELEMS + 2*BK*SB) * 4)   // 70656 B

__global__ __launch_bounds__(256) void gemm_tf32_kernel(
    const float* __restrict__ A, const float* __restrict__ B,
    float* __restrict__ D, int M, int N, int K,
    const float* __restrict__ bias, float alpha, float beta, int flags,
    const float* __restrict__ addA, const float* __restrict__ addC,
    const int* __restrict__ idxFlat)
{
    extern __shared__ float sm[];
    float* AsB = sm;                 // [2][BM][SA]
    float* BsB = sm + AS_ELEMS;      // [2][BK][SB]

    const int tid  = threadIdx.x;
    const int m0   = blockIdx.x * BM;
    const int n0   = blockIdx.y * BN;
    const int warp = tid >> 5;
    const int lane = tid & 31;
    const int wm   = warp >> 1;   // 0..3
    const int wn   = warp & 1;    // 0..1
    const int gid  = lane >> 2;   // 0..7
    const int tig  = lane & 3;    // 0..3

    float acc[2][8][4];
    #pragma unroll
    for (int a = 0; a < 2; a++)
        #pragma unroll
        for (int b = 0; b < 8; b++)
            #pragma unroll
            for (int c = 0; c < 4; c++)
                acc[a][b][c] = 0.f;

    // per-thread load coordinates (fixed)
    const int ar = tid >> 3;            // 0..31  (A row within group of 32)
    const int ac = (tid & 7) * 4;       // col*4
    const int br = tid >> 5;            // 0..7   (B row within group of 8)
    const int bc = (tid & 31) * 4;

    const float* Abase = A + (size_t)m0 * K;
    const float* Bbase = B + n0;

    const int KT = K / BK;

    // ---- prologue: load tile 0 into buf 0 ----
    {
        const float* Ap = Abase;
        #pragma unroll
        for (int i = 0; i < 4; i++)
            cp_async16(&AsB[(ar + i*32) * SA + ac], Ap + (size_t)(ar + i*32) * K + ac);
        const float* Bp = Bbase;
        #pragma unroll
        for (int i = 0; i < 4; i++)
            cp_async16(&BsB[(br + i*8) * SB + bc], Bp + (size_t)(br + i*8) * N + bc);
        CP_COMMIT();
    }

    for (int kt = 0; kt < KT; kt++) {
        const int cur = kt & 1;
        if (kt + 1 < KT) {
            const int nxt = cur ^ 1;
            const float* Ap = Abase + (kt + 1) * BK;
            #pragma unroll
            for (int i = 0; i < 4; i++)
                cp_async16(&AsB[(nxt*BM + ar + i*32) * SA + ac],
                           Ap + (size_t)(ar + i*32) * K + ac);
            const float* Bp = Bbase + (size_t)(kt + 1) * BK * N;
            #pragma unroll
            for (int i = 0; i < 4; i++)
                cp_async16(&BsB[(nxt*BK + br + i*8) * SB + bc],
                           Bp + (size_t)(br + i*8) * N + bc);
            CP_COMMIT();
            CP_WAIT(1);
        } else {
            CP_WAIT(0);
        }
        __syncthreads();

        const float* Asc = AsB + cur * BM * SA;
        const float* Bsc = BsB + cur * BK * SB;

        #pragma unroll
        for (int kk = 0; kk < 4; kk++) {
            uint32_t afr[2][4], bfr[8][2];
            const int kc = kk * 8 + tig;
            #pragma unroll
            for (int mi = 0; mi < 2; mi++) {
                const int r = wm * 32 + mi * 16 + gid;
                afr[mi][0] = __float_as_uint(Asc[(r    ) * SA + kc    ]);
                afr[mi][1] = __float_as_uint(Asc[(r + 8) * SA + kc    ]);
                afr[mi][2] = __float_as_uint(Asc[(r    ) * SA + kc + 4]);
                afr[mi][3] = __float_as_uint(Asc[(r + 8) * SA + kc + 4]);
            }
            #pragma unroll
            for (int ni = 0; ni < 8; ni++) {
                const int c = wn * 64 + ni * 8 + gid;
                bfr[ni][0] = __float_as_uint(Bsc[(kc    ) * SB + c]);
                bfr[ni][1] = __float_as_uint(Bsc[(kc + 4) * SB + c]);
            }
            #pragma unroll
            for (int mi = 0; mi < 2; mi++)
                #pragma unroll
                for (int ni = 0; ni < 8; ni++)
                    mma_tf32(acc[mi][ni], afr[mi], bfr[ni]);
        }
        __syncthreads();
    }

    // ---- epilogue ----
    const int doGelu  = flags & 1;
    const int doRound = flags & 2;
    #pragma unroll
    for (int mi = 0; mi < 2; mi++) {
        #pragma unroll
        for (int h = 0; h < 2; h++) {
            const int m = m0 + wm * 32 + mi * 16 + h * 8 + gid;
            const float* aArow = nullptr;
            const float* aCrow = nullptr;
            if (addA) {
                aArow = addA + (size_t)(m / KNB) * N;
                aCrow = addC + (size_t)idxFlat[m] * N;
            }
            float* Drow = D + (size_t)m * N;
            #pragma unroll
            for (int ni = 0; ni < 8; ni++) {
                const int n = n0 + wn * 64 + ni * 8 + tig * 2;
                float v0 = acc[mi][ni][h * 2 + 0] * alpha;
                float v1 = acc[mi][ni][h * 2 + 1] * alpha;
                if (bias) { v0 += beta * bias[n]; v1 += beta * bias[n + 1]; }
                if (aArow) {
                    v0 += aArow[n] + aCrow[n];
                    v1 += aArow[n + 1] + aCrow[n + 1];
                }
                if (doGelu) { v0 = gelu_exact(v0); v1 = gelu_exact(v1); }
                if (doRound) {
                    v0 = __uint_as_float(f2tf(v0));
                    v1 = __uint_as_float(f2tf(v1));
                }
                *reinterpret_cast<float2*>(Drow + n) = make_float2(v0, v1);
            }
        }
    }
}

// -------- reduction over neighbors: S[i,n] = round(sum_k H2[i,k,n]) --------
__global__ void reduce48_kernel(const float* __restrict__ H2, float* __restrict__ S) {
    int i = blockIdx.x;
    int n = threadIdx.x;                       // 384
    const float* p = H2 + (size_t)i * KNB * NF + n;
    float s = 0.f;
    #pragma unroll
    for (int k = 0; k < KNB; k++) s += p[(size_t)k * NF];
    S[(size_t)i * NF + n] = __uint_as_float(f2tf(s));
}

// -------- layernorm: out = [mask *] LN(a+b)*w + bv ; out2 = round(out) --------
__global__ void ln_kernel(const float* __restrict__ a, const float* __restrict__ b,
                          const float* __restrict__ w, const float* __restrict__ bv,
                          const float* __restrict__ mask,
                          float* __restrict__ out, float* __restrict__ out2)
{
    int i = blockIdx.x;
    int n = threadIdx.x;                       // 384
    float v = a[(size_t)i * NF + n] + b[(size_t)i * NF + n];

    __shared__ float s1[12], s2[12];
    float x1 = v, x2 = v * v;
    #pragma unroll
    for (int o = 16; o; o >>= 1) {
        x1 += __shfl_down_sync(0xFFFFFFFFu, x1, o);
        x2 += __shfl_down_sync(0xFFFFFFFFu, x2, o);
    }
    int wi = n >> 5, li = n & 31;
    if (li == 0) { s1[wi] = x1; s2[wi] = x2; }
    __syncthreads();
    __shared__ float mean_s, rstd_s;
    if (n == 0) {
        float t1 = 0.f, t2 = 0.f;
        #pragma unroll
        for (int j = 0; j < 12; j++) { t1 += s1[j]; t2 += s2[j]; }
        float mu  = t1 * (1.f / NF);
        float var = t2 * (1.f / NF) - mu * mu;
        mean_s = mu;
        rstd_s = rsqrtf(var + 1e-5f);
    }
    __syncthreads();
    float r = (v - mean_s) * rstd_s * w[n] + bv[n];
    if (mask) r *= mask[i];
    out[(size_t)i * NF + n] = r;
    if (out2) out2[(size_t)i * NF + n] = __uint_as_float(f2tf(r));
}

// -------- elementwise tf32 rounding (float4) --------
__global__ void convert_kernel(const float* __restrict__ src, float* __restrict__ dst,
                               int n4)
{
    int i = blockIdx.x * blockDim.x + threadIdx.x;
    if (i < n4) {
        float4 v = reinterpret_cast<const float4*>(src)[i];
        v.x = __uint_as_float(f2tf(v.x));
        v.y = __uint_as_float(f2tf(v.y));
        v.z = __uint_as_float(f2tf(v.z));
        v.w = __uint_as_float(f2tf(v.w));
        reinterpret_cast<float4*>(dst)[i] = v;
    }
}

// copy + rounded copy
__global__ void copy_round_kernel(const float* __restrict__ src,
                                  float* __restrict__ dst,
                                  float* __restrict__ dstR, int n)
{
    int i = blockIdx.x * blockDim.x + threadIdx.x;
    if (i < n) {
        float v = src[i];
        dst[i]  = v;
        dstR[i] = __uint_as_float(f2tf(v));
    }
}

// -------- host orchestration --------
static inline void launch_gemm(const float* A, const float* B, float* D,
                               int M, int N, int K,
                               const float* bias, float alpha, float beta, int flags,
                               const float* addA = nullptr, const float* addC = nullptr,
                               const int* idxFlat = nullptr)
{
    dim3 grid(M / BM, N / BN);
    gemm_tf32_kernel<<<grid, 256, GEMM_SMEM_BYTES>>>(A, B, D, M, N, K, bias,
                                                     alpha, beta, flags,
                                                     addA, addC, idxFlat);
}

static inline void launch_convert(const float* src, float* dst, size_t n) {
    int n4 = (int)(n / 4);
    convert_kernel<<<(n4 + 255) / 256, 256>>>(src, dst, n4);
}

extern "C" void kernel_launch(void* const* d_in, const int* in_sizes, int n_in,
                              void* d_out, int out_size)
{
    (void)in_sizes; (void)n_in; (void)out_size;

    const float* node  = (const float*)d_in[0];
    const float* edges = (const float*)d_in[1];     // [98304, 384]
    const int*   nidx  = (const int*)  d_in[2];     // flat [98304]
    const float* mask  = (const float*)d_in[3];
    const float* w0    = (const float*)d_in[4];     // [L,1536,384]
    const float* b0    = (const float*)d_in[5];
    const float* w1    = (const float*)d_in[6];     // [L,384,384]
    const float* b1    = (const float*)d_in[7];
    const float* w2    = (const float*)d_in[8];
    const float* b2    = (const float*)d_in[9];
    const float* ln1w  = (const float*)d_in[10];
    const float* ln1b  = (const float*)d_in[11];
    const float* dw0   = (const float*)d_in[12];    // [L,384,1536]
    const float* db0   = (const float*)d_in[13];
    const float* dw1   = (const float*)d_in[14];    // [L,1536,384]
    const float* db1   = (const float*)d_in[15];
    const float* ln2w  = (const float*)d_in[16];
    const float* ln2b  = (const float*)d_in[17];

    float *H1, *H2, *ET, *Ab, *Cb, *Sb, *AGG, *X, *Xt, *X1, *X1t, *Dd, *T, *NT;
    float *w0T, *w1T, *w2T, *dw0T, *dw1T;
    cudaGetSymbolAddress((void**)&H1,  g_H1);
    cudaGetSymbolAddress((void**)&H2,  g_H2);
    cudaGetSymbolAddress((void**)&ET,  g_ET);
    cudaGetSymbolAddress((void**)&Ab,  g_A);
    cudaGetSymbolAddress((void**)&Cb,  g_C);
    cudaGetSymbolAddress((void**)&Sb,  g_S);
    cudaGetSymbolAddress((void**)&AGG, g_AGG);
    cudaGetSymbolAddress((void**)&X,   g_X);
    cudaGetSymbolAddress((void**)&Xt,  g_Xt);
    cudaGetSymbolAddress((void**)&X1,  g_X1);
    cudaGetSymbolAddress((void**)&X1t, g_X1t);
    cudaGetSymbolAddress((void**)&Dd,  g_D);
    cudaGetSymbolAddress((void**)&T,   g_T);
    cudaGetSymbolAddress((void**)&NT,  g_NT);
    cudaGetSymbolAddress((void**)&w0T,  g_w0T);
    cudaGetSymbolAddress((void**)&w1T,  g_w1T);
    cudaGetSymbolAddress((void**)&w2T,  g_w2T);
    cudaGetSymbolAddress((void**)&dw0T, g_dw0T);
    cudaGetSymbolAddress((void**)&dw1T, g_dw1T);

    cudaFuncSetAttribute(gemm_tf32_kernel,
                         cudaFuncAttributeMaxDynamicSharedMemorySize,
                         GEMM_SMEM_BYTES);

    // ---- one-time tf32 pre-rounding ----
    launch_convert(edges, ET, (size_t)NROWS * NF);
    launch_convert(node,  NT, (size_t)NN * NF);
    launch_convert(w0,  w0T,  (size_t)LAYERS * MIN_ * NF);
    launch_convert(w1,  w1T,  (size_t)LAYERS * NF * NF);
    launch_convert(w2,  w2T,  (size_t)LAYERS * NF * NF);
    launch_convert(dw0, dw0T, (size_t)LAYERS * NF * MIN_);
    launch_convert(dw1, dw1T, (size_t)LAYERS * MIN_ * NF);

    // x = node_features (fp32 + rounded)
    copy_round_kernel<<<(NN * NF + 255) / 256, 256>>>(node, X, Xt, NN * NF);

    for (int i = 0; i < LAYERS; i++) {
        const float* w0L  = w0T  + (size_t)i * MIN_ * NF;
        const float* b0L  = b0   + (size_t)i * NF;
        const float* w1L  = w1T  + (size_t)i * NF * NF;
        const float* b1L  = b1   + (size_t)i * NF;
        const float* w2L  = w2T  + (size_t)i * NF * NF;
        const float* b2L  = b2   + (size_t)i * NF;
        const float* dw0L = dw0T + (size_t)i * NF * MIN_;
        const float* db0L = db0  + (size_t)i * MIN_;
        const float* dw1L = dw1T + (size_t)i * MIN_ * NF;
        const float* db1L = db1  + (size_t)i * NF;

        // (a) A = x @ W0[0:384] + b0
        launch_gemm(Xt, w0L, Ab, NN, NF, NF, b0L, 1.f, 1.f, 0);
        // (b) C = node @ W0[1152:1536]
        launch_gemm(NT, w0L + (size_t)1152 * NF, Cb, NN, NF, NF, nullptr, 1.f, 0.f, 0);
        // (c) H1 = round(gelu(edges @ W0[384:768] + A[i] + C[idx]))
        launch_gemm(ET, w0L + (size_t)384 * NF, H1, NROWS, NF, NF,
                    nullptr, 1.f, 0.f, 1 | 2, Ab, Cb, nidx);
        // (d) H2 = round(gelu(H1 @ W1 + b1))
        launch_gemm(H1, w1L, H2, NROWS, NF, NF, b1L, 1.f, 1.f, 1 | 2);
        // (e) S = round(sum_k H2)
        reduce48_kernel<<<NN, NF>>>(H2, Sb);
        // (f) AGG = (S @ W2 + 48*b2) / 30
        launch_gemm(Sb, w2L, AGG, NN, NF, NF, b2L, 1.f / 30.f, 48.f / 30.f, 0);
        // (g) x1 = LN(x + AGG)   (fp32 + rounded copy)
        ln_kernel<<<NN, NF>>>(X, AGG, ln1w + (size_t)i * NF, ln1b + (size_t)i * NF,
                              nullptr, X1, X1t);
        // (h) T = round(gelu(x1 @ dense_w0 + db0))
        launch_gemm(X1t, dw0L, T, NN, MIN_, NF, db0L, 1.f, 1.f, 1 | 2);
        // (i) D = T @ dense_w1 + db1
        launch_gemm(T, dw1L, Dd, NN, NF, MIN_, db1L, 1.f, 1.f, 0);
        // (j) x = mask * LN(x1 + D)
        float* xout  = (i == LAYERS - 1) ? (float*)d_out : X;
        float* xout2 = (i == LAYERS - 1) ? nullptr : Xt;
        ln_kernel<<<NN, NF>>>(X1, Dd, ln2w + (size_t)i * NF, ln2b + (size_t)i * NF,
                              mask, xout, xout2);
    }
}